// round 7
// baseline (speedup 1.0000x reference)
#include <cuda_runtime.h>
#include <cuda_fp16.h>
#include <math.h>
#include <stdint.h>

#define NQ 8192
#define NC 8192
#define DIM 256

// E hi-fp16 images: per (ntile 0..31, kchunk 0..7) 1024 uint4 (16KB).
// uint4 at [n*4 + (s ^ ((n>>1)&3))] components c: H2 of k_local = 2s + 8c.
__device__ uint4 g_ehi_img[32 * 8 * 1024];     // 4 MB
__device__ float g_enorm[NC];
__device__ float g_margin[NQ];
__device__ int   g_counts[NC];
__device__ float g_partial[NQ];
__device__ float g_sbv[2 * NQ];                // per-strip best
__device__ float g_ssv[2 * NQ];                // per-strip second
__device__ int   g_sbi[2 * NQ];
__device__ int   g_outidx[NQ];
__device__ int   g_flagq[NQ];
__device__ int   g_flagslot[NQ];
__device__ int   g_flagcount;
__device__ float g_resv[NQ * 64];              // rescore partials per code-tile
__device__ int   g_resi[NQ * 64];

#define ES_U4 4096                             // X image: 4096 uint4 (64KB)
#define STAGE_U4 1024                          // 16KB per E stage
#define SMEM_BYTES ((4096 + 3 * 1024) * 16)    // 114688 B
#define RS_SMEM ((32768 + 2048 + 2048) * 4)    // 147456 B

// ---------------------------------------------------------------------------
__device__ __forceinline__ void mma16(float* c, uint32_t a0, uint32_t a1,
                                      uint32_t a2, uint32_t a3,
                                      uint32_t b0, uint32_t b1) {
    asm volatile(
        "mma.sync.aligned.m16n8k16.row.col.f32.f16.f16.f32 "
        "{%0,%1,%2,%3}, {%4,%5,%6,%7}, {%8,%9}, {%0,%1,%2,%3};"
        : "+f"(c[0]), "+f"(c[1]), "+f"(c[2]), "+f"(c[3])
        : "r"(a0), "r"(a1), "r"(a2), "r"(a3), "r"(b0), "r"(b1));
}

__device__ __forceinline__ uint32_t pack_h2(float v0, float v1) {
    __half2 h = __halves2half2(__float2half_rn(v0), __float2half_rn(v1));
    return *(uint32_t*)&h;
}

__device__ __forceinline__ void cp16(uint32_t daddr, const void* src) {
    asm volatile("cp.async.cg.shared.global [%0], [%1], 16;" :: "r"(daddr), "l"(src));
}
__device__ __forceinline__ uint32_t smem_u32(const void* p) {
    uint32_t a;
    asm("{ .reg .u64 t; cvta.to.shared.u64 t, %1; cvt.u32.u64 %0, t; }" : "=r"(a) : "l"(p));
    return a;
}

// ---------------------------------------------------------------------------
// k_split: grid (8192, 2). y=0: E row -> enorm + hi-image + zero counts.
//          y=1: X row -> sound screen margin from ||x||.
// ---------------------------------------------------------------------------
__global__ void k_split(const float* __restrict__ X, const float* __restrict__ E) {
    __shared__ float buf[256];
    __shared__ float red[256];
    const int row = blockIdx.x;
    const int t = threadIdx.x;
    const float* src = (blockIdx.y == 0) ? E : X;
    float v = src[(size_t)row * DIM + t];
    buf[t] = v;
    red[t] = v * v;
    __syncthreads();
    #pragma unroll
    for (int off = 128; off > 0; off >>= 1) {
        if (t < off) red[t] += red[t + off];
        __syncthreads();
    }
    if (blockIdx.y == 0) {
        if (row < 32) g_counts[row * 256 + t] = 0;
        if (row == 0 && t == 0) g_flagcount = 0;
        if (t == 0) g_enorm[row] = red[0];
        if (t < 128) {
            uint32_t h2 = pack_h2(buf[2 * t], buf[2 * t + 1]);
            const int kc = t >> 4;             // chunk 0..7
            const int p  = t & 15;             // pair within chunk
            const int s  = p & 3;
            const int c  = p >> 2;
            const int n  = row & 255;
            const int ntg = row >> 8;
            uint32_t* dst = (uint32_t*)&g_ehi_img[(ntg * 8 + kc) * 1024 +
                                                  n * 4 + (s ^ ((n >> 1) & 3))];
            dst[c] = h2;
        }
    } else {
        // |dot_exact - dot_hh| <= 2^-10 * ||x|| * ||e|| (+ slop); ||e|| <= 1+1e-7
        if (t == 0) g_margin[row] = 1.0254e-3f * sqrtf(red[0]) + 1e-4f;
    }
}

// ---------------------------------------------------------------------------
// k_gemm: 1-pass fp16 screen GEMM + fused top-2 argmin.
// Grid (64 q-tiles, 2 strips) x 256. CTA 128q x 256n x 16 ctiles.
// 8 warps = 2(m:64) x 4(n:64). Per kc(k32): 8 A-LDS + 8 B-LDS + 64 HMMA/warp.
// ---------------------------------------------------------------------------
__global__ __launch_bounds__(256, 1) void k_gemm(const float* __restrict__ X) {
    extern __shared__ uint4 smem_u4[];

    const int tid   = threadIdx.x;
    const int lane  = tid & 31;
    const int wid   = tid >> 5;
    const int warpm = wid & 1;
    const int warpn = wid >> 1;
    const int gid   = lane >> 2;
    const int tig   = lane & 3;
    const int q0    = blockIdx.x * 128;
    const int strip = blockIdx.y;

    const uint32_t es_base = smem_u32(smem_u4 + ES_U4);
    const uint4* esrc0 = g_ehi_img + (size_t)(strip * 16) * 8 * 1024;

    // prologue: async-stage E chunks 0, 1
    #pragma unroll
    for (int j = 0; j < 4; j++)
        cp16(es_base + (uint32_t)(tid + j * 256) * 16, esrc0 + tid + j * 256);
    asm volatile("cp.async.commit_group;" ::: "memory");
    #pragma unroll
    for (int j = 0; j < 4; j++)
        cp16(es_base + (uint32_t)(STAGE_U4 + tid + j * 256) * 16,
             esrc0 + 1024 + tid + j * 256);
    asm volatile("cp.async.commit_group;" ::: "memory");

    // X tile -> hi-fp16 image in SMEM (overlaps cp.async)
    #pragma unroll
    for (int i = 0; i < 32; i++) {
        int idx = tid + i * 256;
        int r = idx >> 6;
        int j = idx & 63;
        float4 v = *(const float4*)(X + (size_t)(q0 + r) * DIM + j * 4);
        uint32_t h2a = pack_h2(v.x, v.y);
        uint32_t h2b = pack_h2(v.z, v.w);
        #pragma unroll
        for (int pp = 0; pp < 2; pp++) {
            int P = 2 * j + pp;
            int kc = P >> 4, p = P & 15, s = p & 3, c = p >> 2;
            uint32_t* d =
                (uint32_t*)&smem_u4[kc * 512 + r * 4 + (s ^ ((r >> 1) & 3))];
            d[c] = pp ? h2b : h2a;
        }
    }

    float bestv[8], secv[8];
    int   besti[8];
    #pragma unroll
    for (int i = 0; i < 8; i++) { bestv[i] = INFINITY; secv[i] = INFINITY; besti[i] = 0; }

    const int cbase0 = strip * 4096;

    for (int ct = 0; ct < 16; ct++) {
        float c[4][8][4];
        #pragma unroll
        for (int mt = 0; mt < 4; mt++)
            #pragma unroll
            for (int nt = 0; nt < 8; nt++)
                #pragma unroll
                for (int r = 0; r < 4; r++) c[mt][nt][r] = 0.f;

        for (int kc = 0; kc < 8; kc++) {
            const int cc = ct * 8 + kc;
            asm volatile("cp.async.wait_group 1;" ::: "memory");
            __syncthreads();

            if (cc + 2 < 128) {
                const uint32_t db = es_base + (uint32_t)(((cc + 2) % 3) * STAGE_U4) * 16;
                const uint4* src = esrc0 + (size_t)(cc + 2) * 1024;
                #pragma unroll
                for (int j = 0; j < 4; j++)
                    cp16(db + (uint32_t)(tid + j * 256) * 16, src + tid + j * 256);
            }
            asm volatile("cp.async.commit_group;" ::: "memory");

            const uint4* EsB = smem_u4 + ES_U4 + (cc % 3) * STAGE_U4;
            uint4 A0[4], A1[4];
            #pragma unroll
            for (int mt = 0; mt < 4; mt++) {
                const int r = warpm * 64 + mt * 16 + gid;
                const int sw = tig ^ ((r >> 1) & 3);    // same for r and r+8
                A0[mt] = smem_u4[kc * 512 + r * 4 + sw];
                A1[mt] = smem_u4[kc * 512 + (r + 8) * 4 + sw];
            }
            #pragma unroll
            for (int nt = 0; nt < 8; nt++) {
                const int n = warpn * 64 + nt * 8 + gid;
                uint4 B = EsB[n * 4 + (tig ^ ((n >> 1) & 3))];
                #pragma unroll
                for (int mt = 0; mt < 4; mt++) {
                    mma16(c[mt][nt], A0[mt].x, A1[mt].x, A0[mt].y, A1[mt].y, B.x, B.y);
                    mma16(c[mt][nt], A0[mt].z, A1[mt].z, A0[mt].w, A1[mt].w, B.z, B.w);
                }
            }
        }

        // fused top-2 epilogue
        const int cb = cbase0 + ct * 256 + warpn * 64;
        #pragma unroll
        for (int nt = 0; nt < 8; nt++) {
            const int col0 = cb + nt * 8 + tig * 2;
            const float en0 = __ldg(&g_enorm[col0]);
            const float en1 = __ldg(&g_enorm[col0 + 1]);
            #pragma unroll
            for (int mt = 0; mt < 4; mt++) {
                #pragma unroll
                for (int rh = 0; rh < 2; rh++) {
                    const int sl = mt * 2 + rh;
                    float d0 = fmaf(-2.f, c[mt][nt][rh * 2 + 0], en0);
                    float d1 = fmaf(-2.f, c[mt][nt][rh * 2 + 1], en1);
                    if (d0 < bestv[sl]) { secv[sl] = bestv[sl]; bestv[sl] = d0; besti[sl] = col0; }
                    else if (d0 < secv[sl]) secv[sl] = d0;
                    if (d1 < bestv[sl]) { secv[sl] = bestv[sl]; bestv[sl] = d1; besti[sl] = col0 + 1; }
                    else if (d1 < secv[sl]) secv[sl] = d1;
                }
            }
        }
    }

    // cross-thread top-2 reduce (16 contributors per query row)
    __syncthreads();
    float* rv = (float*)(smem_u4 + ES_U4);          // 2048
    float* sv = rv + 2048;                          // 2048
    int*   ri = (int*)(sv + 2048);                  // 2048
    const int slot16 = warpn * 4 + tig;
    #pragma unroll
    for (int mt = 0; mt < 4; mt++)
        #pragma unroll
        for (int rh = 0; rh < 2; rh++) {
            const int row = warpm * 64 + mt * 16 + rh * 8 + gid;
            rv[row * 16 + slot16] = bestv[mt * 2 + rh];
            sv[row * 16 + slot16] = secv[mt * 2 + rh];
            ri[row * 16 + slot16] = besti[mt * 2 + rh];
        }
    __syncthreads();
    if (tid < 128) {
        float B = rv[tid * 16], S = sv[tid * 16];
        int   I = ri[tid * 16];
        #pragma unroll
        for (int s = 1; s < 16; s++) {
            float b = rv[tid * 16 + s], s2 = sv[tid * 16 + s];
            int   i = ri[tid * 16 + s];
            float newS = fminf(fmaxf(B, b), fminf(S, s2));
            if (b < B || (b == B && i < I)) { B = b; I = i; }
            S = newS;
        }
        g_sbv[strip * NQ + q0 + tid] = B;
        g_ssv[strip * NQ + q0 + tid] = S;
        g_sbi[strip * NQ + q0 + tid] = I;
    }
}

// ---------------------------------------------------------------------------
// k_flag: combine strips; certainty test; build flagged-query list.
// ---------------------------------------------------------------------------
__global__ void k_flag() {
    const int n = blockIdx.x * 256 + threadIdx.x;
    float b0 = g_sbv[n], b1 = g_sbv[NQ + n];
    float s0 = g_ssv[n], s1 = g_ssv[NQ + n];
    int   i0 = g_sbi[n], i1 = g_sbi[NQ + n];
    float gb;
    int gbi;
    if (b1 < b0 || (b1 == b0 && i1 < i0)) { gb = b1; gbi = i1; }
    else                                  { gb = b0; gbi = i0; }
    float gs = fminf(fminf(s0, s1), fmaxf(b0, b1));
    g_outidx[n] = gbi;
    if (gs - gb <= 2.f * g_margin[n]) {
        int s = atomicAdd(&g_flagcount, 1);
        g_flagq[s] = n;
        g_flagslot[n] = s;
    } else {
        g_flagslot[n] = -1;
    }
}

// ---------------------------------------------------------------------------
// k_rescore: exact fp32 distances for flagged queries, tiled over codes.
// Grid 64 blocks (128 codes each) x 256 threads; batches of 8 queries.
// ---------------------------------------------------------------------------
__global__ __launch_bounds__(256, 1) void k_rescore(const float* __restrict__ X,
                                                    const float* __restrict__ E) {
    extern __shared__ float rs[];
    float* Et = rs;                    // [k 0..255][code 0..127]  (32768)
    float* xb = rs + 32768;            // 8 x-rows / reuse as dvals (2048)
    float* sd = xb + 2048;             // partial dots [tid][8]    (2048)

    const int tid = threadIdx.x;
    const int c0 = blockIdx.x * 128;

    // load E tile transposed: Et[k*128 + c]
    #pragma unroll
    for (int i = 0; i < 32; i++) {
        int idx = tid + i * 256;       // float4 slots over 128 rows x 64
        int r = idx >> 6;
        int j = idx & 63;
        float4 v = *(const float4*)(E + (size_t)(c0 + r) * DIM + j * 4);
        Et[(4 * j + 0) * 128 + r] = v.x;
        Et[(4 * j + 1) * 128 + r] = v.y;
        Et[(4 * j + 2) * 128 + r] = v.z;
        Et[(4 * j + 3) * 128 + r] = v.w;
    }
    __syncthreads();

    const int nf = g_flagcount;
    const int code = tid & 127;
    const int h = tid >> 7;
    const int wid = tid >> 5;
    const int lane = tid & 31;

    for (int s0i = 0; s0i < nf; s0i += 8) {
        const int nb = min(8, nf - s0i);
        for (int b = 0; b < nb; b++)
            xb[b * 256 + tid] = X[(size_t)g_flagq[s0i + b] * DIM + tid];
        __syncthreads();

        float acc[8];
        #pragma unroll
        for (int b = 0; b < 8; b++) acc[b] = 0.f;
        for (int k = 0; k < 128; k++) {
            float ev = Et[(h * 128 + k) * 128 + code];
            #pragma unroll
            for (int b = 0; b < 8; b++)
                acc[b] = fmaf(xb[b * 256 + h * 128 + k], ev, acc[b]);
        }
        #pragma unroll
        for (int b = 0; b < 8; b++) sd[tid * 8 + b] = acc[b];
        __syncthreads();

        if (tid < 128) {
            float en = __ldg(&g_enorm[c0 + tid]);
            for (int b = 0; b < nb; b++) {
                float dot = sd[tid * 8 + b] + sd[(tid + 128) * 8 + b];
                xb[b * 128 + tid] = fmaf(-2.f, dot, en);   // reuse xb as dvals
            }
        }
        __syncthreads();

        if (wid < nb) {
            float bv = INFINITY;
            int bi = 0;
            #pragma unroll
            for (int i = 0; i < 4; i++) {
                int cidx = i * 32 + lane;                  // increasing order
                float v = xb[wid * 128 + cidx];
                if (v < bv) { bv = v; bi = cidx; }
            }
            #pragma unroll
            for (int off = 16; off > 0; off >>= 1) {
                float ov = __shfl_down_sync(0xffffffffu, bv, off);
                int   oi = __shfl_down_sync(0xffffffffu, bi, off);
                if (ov < bv || (ov == bv && oi < bi)) { bv = ov; bi = oi; }
            }
            if (lane == 0) {
                g_resv[(s0i + wid) * 64 + blockIdx.x] = bv;
                g_resi[(s0i + wid) * 64 + blockIdx.x] = c0 + bi;
            }
        }
        __syncthreads();
    }
}

// ---------------------------------------------------------------------------
// k_gather: warp per query row. Resolve index (screen or rescore), quantized
// output, loss partials, histogram. grid = 1024 x 256.
// ---------------------------------------------------------------------------
__global__ void k_gather(const float* __restrict__ X, const float* __restrict__ E,
                         float* __restrict__ out) {
    const int w = threadIdx.x >> 5;
    const int lane = threadIdx.x & 31;
    const int n = blockIdx.x * 8 + w;
    const int fs = g_flagslot[n];
    int idx;
    if (fs >= 0) {
        float v0 = g_resv[fs * 64 + lane];
        int   i0 = g_resi[fs * 64 + lane];
        float v1 = g_resv[fs * 64 + 32 + lane];
        int   i1 = g_resi[fs * 64 + 32 + lane];
        if (v1 < v0 || (v1 == v0 && i1 < i0)) { v0 = v1; i0 = i1; }
        #pragma unroll
        for (int off = 16; off > 0; off >>= 1) {
            float ov = __shfl_down_sync(0xffffffffu, v0, off);
            int   oi = __shfl_down_sync(0xffffffffu, i0, off);
            if (ov < v0 || (ov == v0 && oi < i0)) { v0 = ov; i0 = oi; }
        }
        idx = __shfl_sync(0xffffffffu, i0, 0);
    } else {
        idx = g_outidx[n];
    }

    const float4* qe = (const float4*)(E + (size_t)idx * DIM);
    const float4* xr = (const float4*)(X + (size_t)n * DIM);
    float4* o = (float4*)(out + (size_t)n * DIM);
    float s = 0.f;
    #pragma unroll
    for (int h = 0; h < 2; h++) {
        int j = lane + h * 32;
        float4 q = qe[j], x = xr[j];
        float dx = q.x - x.x, dy = q.y - x.y, dz = q.z - x.z, dw = q.w - x.w;
        float4 r;
        r.x = x.x + dx; r.y = x.y + dy; r.z = x.z + dz; r.w = x.w + dw;
        o[j] = r;
        s += dx * dx + dy * dy + dz * dz + dw * dw;
    }
    #pragma unroll
    for (int off = 16; off > 0; off >>= 1)
        s += __shfl_down_sync(0xffffffffu, s, off);
    if (lane == 0) {
        g_partial[n] = s;
        atomicAdd(&g_counts[idx], 1);
    }
}

// ---------------------------------------------------------------------------
// k_final: deterministic loss + perplexity.
// ---------------------------------------------------------------------------
__global__ void k_final(float* __restrict__ out, int out_size) {
    __shared__ float sm[1024];
    const int t = threadIdx.x;

    float s = 0.f;
    for (int i = t; i < NQ; i += 1024) s += g_partial[i];
    sm[t] = s;
    __syncthreads();
    #pragma unroll
    for (int off = 512; off > 0; off >>= 1) {
        if (t < off) sm[t] += sm[t + off];
        __syncthreads();
    }
    const float total = sm[0];
    __syncthreads();

    float hsum = 0.f;
    for (int i = t; i < NC; i += 1024) {
        float p = (float)g_counts[i] * (1.0f / (float)NQ);
        hsum += p * logf(p + 1e-10f);
    }
    sm[t] = hsum;
    __syncthreads();
    #pragma unroll
    for (int off = 512; off > 0; off >>= 1) {
        if (t < off) sm[t] += sm[t + off];
        __syncthreads();
    }

    if (t == 0) {
        float mean_sq = total / (float)((size_t)NQ * DIM);
        float loss = mean_sq + 0.25f * mean_sq;
        float perplexity = expf(-sm[0]);
        if (out_size >= NQ * DIM + 2) {
            out[(size_t)NQ * DIM]     = loss;
            out[(size_t)NQ * DIM + 1] = perplexity;
        }
    }
}

// ---------------------------------------------------------------------------
extern "C" void kernel_launch(void* const* d_in, const int* in_sizes, int n_in,
                              void* d_out, int out_size) {
    const float* X = (const float*)d_in[0];   // [32,256,256] -> [8192,256]
    const float* E = (const float*)d_in[1];   // [8192,256]
    float* out = (float*)d_out;

    cudaFuncSetAttribute(k_gemm, cudaFuncAttributeMaxDynamicSharedMemorySize, SMEM_BYTES);
    cudaFuncSetAttribute(k_rescore, cudaFuncAttributeMaxDynamicSharedMemorySize, RS_SMEM);

    k_split<<<dim3(NQ, 2), 256>>>(X, E);
    k_gemm<<<dim3(64, 2), 256, SMEM_BYTES>>>(X);
    k_flag<<<32, 256>>>();
    k_rescore<<<64, 256, RS_SMEM>>>(X, E);
    k_gather<<<1024, 256>>>(X, E, out);
    k_final<<<1, 1024>>>(out, out_size);
}